// round 8
// baseline (speedup 1.0000x reference)
#include <cuda_runtime.h>
#include <cuda_bf16.h>
#include <math.h>
#include <stdint.h>

// ---------------------------------------------------------------------------
// Problem constants
// ---------------------------------------------------------------------------
#define Hn   512
#define DHn  2048
#define Bn   32
#define Sn   2048
#define Mrows (Sn * Bn)       // 65536

// GEMM tiling: 128x128 tile, KC=32, 3-stage, 2 CTAs/SM
#define TM 128
#define TN 128
#define KC 32
#define NCHUNK (Hn / KC)      // 16
#define NBLK (Hn / TN)        // 4
#define NTHREADS 256
#define NSTAGE 3

// smem: A tile 128x32 f32 (16KB) + B tile 128x32 f32 (16KB) per stage
#define OFF_A 0
#define OFF_B 16384
#define STG_BYTES 32768
#define SMEM_TOTAL (NSTAGE * STG_BYTES)   // 98304 -> 2 CTAs/SM (192KB)

// ---------------------------------------------------------------------------
// Device scratch
// ---------------------------------------------------------------------------
__device__ __align__(16) float g_hpart[Hn * Bn];            // [d][b]
__device__ __align__(16) float g_partial[NBLK * Bn * Sn];   // [j][b][s]
__device__ __align__(16) float g_Wt[Hn * Hn];               // [n][k], tf32-rounded

// ---------------------------------------------------------------------------
// PTX helpers (compute_100-safe, sm_80-era)
// ---------------------------------------------------------------------------
__device__ __forceinline__ uint32_t smem_u32(const void* p) {
    uint32_t a;
    asm("{ .reg .u64 t; cvta.to.shared.u64 t, %1; cvt.u32.u64 %0, t; }"
        : "=r"(a) : "l"(p));
    return a;
}

#define CP16(daddr, sptr) \
    asm volatile("cp.async.cg.shared.global [%0], [%1], 16;" \
        :: "r"((uint32_t)(daddr)), "l"(__cvta_generic_to_global(sptr)))
#define CP_COMMIT() asm volatile("cp.async.commit_group;" ::: "memory")
#define CP_WAIT1()  asm volatile("cp.async.wait_group 1;" ::: "memory")
#define CP_WAIT0()  asm volatile("cp.async.wait_group 0;" ::: "memory")

#define LDSM4(r, addr) \
    asm volatile("ldmatrix.sync.aligned.m8n8.x4.shared.b16 {%0,%1,%2,%3}, [%4];" \
        : "=r"((r)[0]), "=r"((r)[1]), "=r"((r)[2]), "=r"((r)[3]) \
        : "r"((uint32_t)(addr)))

#define MMA_TF32(d, a, b0, b1) \
    asm volatile( \
        "mma.sync.aligned.m16n8k8.row.col.f32.tf32.tf32.f32 " \
        "{%0,%1,%2,%3}, {%4,%5,%6,%7}, {%8,%9}, {%0,%1,%2,%3};" \
        : "+f"((d)[0]), "+f"((d)[1]), "+f"((d)[2]), "+f"((d)[3]) \
        : "r"((a)[0]), "r"((a)[1]), "r"((a)[2]), "r"((a)[3]), \
          "r"(b0), "r"(b1))

#define CVT_TF32_IP(x) \
    asm volatile("cvt.rna.tf32.f32 %0, %0;" : "+r"(x))

#define CVT_TF32(dst, src) \
    asm volatile("cvt.rna.tf32.f32 %0, %1;" : "=r"(dst) : "r"(src))

// ---------------------------------------------------------------------------
// FMA-only fast tanh (no MUFU)
// ---------------------------------------------------------------------------
__device__ __forceinline__ float fast_tanh(float x) {
    const float C = 7.90531110763549805f;
    float xc = fmaxf(-C, fminf(C, x));
    float x2 = xc * xc;
    float p = -2.76076847742355e-16f;
    p = fmaf(p, x2, 2.00018790482477e-13f);
    p = fmaf(p, x2, -8.60467152213735e-11f);
    p = fmaf(p, x2, 5.12229709037114e-08f);
    p = fmaf(p, x2, 1.48572235717979e-05f);
    p = fmaf(p, x2, 6.37261928875436e-04f);
    p = fmaf(p, x2, 4.89352455891786e-03f);
    p = p * xc;
    float q = 1.19825839466702e-06f;
    q = fmaf(q, x2, 1.18534705686654e-04f);
    q = fmaf(q, x2, 2.26843463243900e-03f);
    q = fmaf(q, x2, 4.89352518554385e-03f);
    float y = __uint_as_float(0x7EF311C3u - __float_as_uint(q));
    y = y * fmaf(-q, y, 2.0f);
    y = y * fmaf(-q, y, 2.0f);
    y = y * fmaf(-q, y, 2.0f);
    return p * y;
}

// ---------------------------------------------------------------------------
// Kernel D: no-op (shifts launch index so ncu captures main_kernel)
// ---------------------------------------------------------------------------
__global__ void dummy_kernel() {}

// ---------------------------------------------------------------------------
// Kernel 0: W_e -> transposed, tf32-rounded fp32  g_Wt[n][k]
// ---------------------------------------------------------------------------
__global__ __launch_bounds__(256) void wconv_kernel(const float* __restrict__ W_attn)
{
    int idx = blockIdx.x * 256 + threadIdx.x;   // 0..262143
    int n = idx & (Hn - 1);                     // coalesced read along n
    int k = idx >> 9;
    uint32_t w = __float_as_uint(W_attn[(size_t)(DHn + k) * Hn + n]);
    uint32_t r;
    CVT_TF32(r, w);
    g_Wt[(size_t)n * Hn + k] = __uint_as_float(r);
}

// ---------------------------------------------------------------------------
// Kernel 1: hpart[d][b] = hidden[b] @ W_h[:,d] + b_attn[d]   (transposed out)
// ---------------------------------------------------------------------------
__global__ __launch_bounds__(512) void hpart_kernel(
    const float* __restrict__ hidden,
    const float* __restrict__ W_attn,
    const float* __restrict__ b_attn)
{
    __shared__ float red[3 * 128];
    int tid = threadIdx.x;
    int dl = tid & 127;
    int kh = tid >> 7;                   // 0..3
    int b = blockIdx.x;
    int d = blockIdx.y * 128 + dl;

    const float* __restrict__ hrow = hidden + b * DHn + kh * 512;
    const float* __restrict__ Wp = W_attn + (size_t)(kh * 512) * Hn + d;
    float acc = 0.0f;
#pragma unroll 8
    for (int k = 0; k < 512; k++) {
        acc = fmaf(hrow[k], Wp[(size_t)k * Hn], acc);
    }
    if (kh > 0) red[(kh - 1) * 128 + dl] = acc;
    __syncthreads();
    if (kh == 0) {
        acc += red[dl] + red[128 + dl] + red[256 + dl] + b_attn[d];
        g_hpart[(size_t)d * Bn + b] = acc;
    }
}

// ---------------------------------------------------------------------------
// Kernel 2: single-pass tf32 mma GEMM + tanh + v-dot
// grid (NBLK, 512); 256 threads (8 warps: 2M x 4N); tile 128x128, KC=32
// 3-stage cp.async (one __syncthreads per chunk), 2 CTAs/SM
// ---------------------------------------------------------------------------
__global__ __launch_bounds__(NTHREADS, 2) void main_kernel(
    const float* __restrict__ enc,    // (65536, 512) fp32
    const float* __restrict__ v)
{
    extern __shared__ char smem[];
    const uint32_t sb = smem_u32(smem);
    const int tid = threadIdx.x;
    const int wid = tid >> 5;
    const int lane = tid & 31;
    const int warp_m = wid >> 2;          // 0..1
    const int warp_n = wid & 3;           // 0..3
    const int colbase = blockIdx.x * TN;
    const int rowbase = blockIdx.y * TM;

    float acc[4][4][4];
#pragma unroll
    for (int mt = 0; mt < 4; mt++)
#pragma unroll
        for (int nt = 0; nt < 4; nt++)
#pragma unroll
            for (int q = 0; q < 4; q++) acc[mt][nt][q] = 0.0f;

    // cp.async one K-chunk (A 128x32 f32 + B 128x32 f32) into stage s.
    // Row = 128B (8 x 16B units); swizzle: phys_unit = u ^ (row & 7)
    auto load_chunk = [&](int c, int s) {
        const int kb = c * KC;
        const uint32_t stg = sb + s * STG_BYTES;
#pragma unroll
        for (int j = 0; j < 4; j++) {           // A: 1024 units
            int idx = tid + j * NTHREADS;
            int row = idx >> 3;
            int u = idx & 7;
            uint32_t doff = (uint32_t)(row * 128 + 16 * (u ^ (row & 7)));
            CP16(stg + OFF_A + doff, enc + (size_t)(rowbase + row) * Hn + kb + u * 4);
        }
#pragma unroll
        for (int j = 0; j < 4; j++) {           // B: 1024 units
            int idx = tid + j * NTHREADS;
            int row = idx >> 3;
            int u = idx & 7;
            uint32_t doff = (uint32_t)(row * 128 + 16 * (u ^ (row & 7)));
            CP16(stg + OFF_B + doff, g_Wt + (size_t)(colbase + row) * Hn + kb + u * 4);
        }
    };

    load_chunk(0, 0);
    CP_COMMIT();
    load_chunk(1, 1);
    CP_COMMIT();

    // ldmatrix per-lane addressing (32-bit elements via b16 ldmatrix)
    const int a_r  = ((lane >> 3) & 1) * 8 + (lane & 7);  // row within m16
    const int a_uo = (lane >> 4);                         // 16B-unit offset 0/1
    const int b_r  = ((lane >> 4) & 1) * 8 + (lane & 7);  // n within 16
    const int b_uo = ((lane >> 3) & 1);

    int stage_c = 0;        // stage holding chunk c
    int stage_l = 2;        // stage for chunk c+2

    for (int c = 0; c < NCHUNK; c++) {
        if (c < NCHUNK - 1) { CP_WAIT1(); } else { CP_WAIT0(); }
        __syncthreads();
        if (c + 2 < NCHUNK) {
            load_chunk(c + 2, stage_l);
            CP_COMMIT();
        }

        const uint32_t stg = sb + stage_c * STG_BYTES;
        const uint32_t sA = stg + OFF_A;
        const uint32_t sB = stg + OFF_B;

#pragma unroll
        for (int ks = 0; ks < 4; ks++) {        // 4 k8-steps per 32-chunk
            const int ub = ks * 2;
            uint32_t afr[4][4], bfr[2][4];
#pragma unroll
            for (int mt = 0; mt < 4; mt++) {
                int row = warp_m * 64 + mt * 16 + a_r;
                uint32_t off = (uint32_t)(row * 128 + 16 * ((ub + a_uo) ^ (row & 7)));
                LDSM4(afr[mt], sA + off);
            }
#pragma unroll
            for (int pr = 0; pr < 2; pr++) {
                int n = warp_n * 32 + pr * 16 + b_r;
                uint32_t off = (uint32_t)(n * 128 + 16 * ((ub + b_uo) ^ (n & 7)));
                LDSM4(bfr[pr], sB + off);
            }
#pragma unroll
            for (int mt = 0; mt < 4; mt++)
#pragma unroll
                for (int q = 0; q < 4; q++)
                    CVT_TF32_IP(afr[mt][q]);
#pragma unroll
            for (int mt = 0; mt < 4; mt++) {
#pragma unroll
                for (int pr = 0; pr < 2; pr++) {
                    MMA_TF32(acc[mt][pr * 2 + 0], afr[mt], bfr[pr][0], bfr[pr][1]);
                    MMA_TF32(acc[mt][pr * 2 + 1], afr[mt], bfr[pr][2], bfr[pr][3]);
                }
            }
        }

        stage_c = (stage_c == 2) ? 0 : stage_c + 1;
        stage_l = (stage_l == 2) ? 0 : stage_l + 1;
    }

    __syncthreads();   // all reads done before smem reuse

    // ---- Epilogue: hp[col][b] (16KB), v (512B), red (128x17 = 8.7KB)
    float* hp_s = (float*)smem;                        // 128*32
    float* v_s  = (float*)(smem + 16384);              // 128
    float* red  = (float*)(smem + 17408);              // 128*17

    for (int i = tid; i < TN * Bn; i += NTHREADS)
        hp_s[i] = g_hpart[(size_t)colbase * Bn + i];
    if (tid < TN) v_s[tid] = v[colbase + tid];
    __syncthreads();

    const int tg = lane & 3;
    const int gid = lane >> 2;
#pragma unroll
    for (int mt = 0; mt < 4; mt++) {
        int r0 = warp_m * 64 + mt * 16 + gid;
        int r1 = r0 + 8;
        int b0 = r0 & 31;
        int b1 = r1 & 31;
        float s0 = 0.0f, s1 = 0.0f;
#pragma unroll
        for (int nt = 0; nt < 4; nt++) {
            int c0 = warp_n * 32 + nt * 8 + tg * 2;
            float v0 = v_s[c0], v1 = v_s[c0 + 1];
            float x00 = acc[mt][nt][0] + hp_s[c0 * 32 + b0];
            float x10 = acc[mt][nt][1] + hp_s[(c0 + 1) * 32 + b0];
            float x01 = acc[mt][nt][2] + hp_s[c0 * 32 + b1];
            float x11 = acc[mt][nt][3] + hp_s[(c0 + 1) * 32 + b1];
            s0 = fmaf(fast_tanh(x00), v0, s0);
            s0 = fmaf(fast_tanh(x10), v1, s0);
            s1 = fmaf(fast_tanh(x01), v0, s1);
            s1 = fmaf(fast_tanh(x11), v1, s1);
        }
        red[r0 * 17 + warp_n * 4 + tg] = s0;
        red[r1 * 17 + warp_n * 4 + tg] = s1;
    }
    __syncthreads();

    if (tid < TM) {
        float s = 0.0f;
#pragma unroll
        for (int j = 0; j < 16; j++) s += red[tid * 17 + j];
        int b = tid & 31;
        int seq = blockIdx.y * (TM / Bn) + (tid >> 5);
        g_partial[blockIdx.x * (Bn * Sn) + b * Sn + seq] = s;
    }
}

// ---------------------------------------------------------------------------
// Kernel 3: sum 4 partials + softmax over s
// ---------------------------------------------------------------------------
__global__ __launch_bounds__(512) void softmax_kernel(float* __restrict__ out)
{
    const int b = blockIdx.x;
    const int tid = threadIdx.x;
    __shared__ float logits[Sn];
    __shared__ float redbuf[512];

    for (int s = tid; s < Sn; s += 512) {
        float t = 0.0f;
#pragma unroll
        for (int j = 0; j < NBLK; j++) t += g_partial[j * (Bn * Sn) + b * Sn + s];
        logits[s] = t;
    }
    __syncthreads();

    float m = -INFINITY;
    for (int s = tid; s < Sn; s += 512) m = fmaxf(m, logits[s]);
    redbuf[tid] = m;
    __syncthreads();
    for (int off = 256; off > 0; off >>= 1) {
        if (tid < off) redbuf[tid] = fmaxf(redbuf[tid], redbuf[tid + off]);
        __syncthreads();
    }
    m = redbuf[0];
    __syncthreads();

    float sum = 0.0f;
    for (int s = tid; s < Sn; s += 512) {
        float e = expf(logits[s] - m);
        logits[s] = e;
        sum += e;
    }
    redbuf[tid] = sum;
    __syncthreads();
    for (int off = 256; off > 0; off >>= 1) {
        if (tid < off) redbuf[tid] += redbuf[tid + off];
        __syncthreads();
    }
    const float inv = 1.0f / redbuf[0];
    __syncthreads();

    for (int s = tid; s < Sn; s += 512) {
        out[b * Sn + s] = logits[s] * inv;
    }
}

// ---------------------------------------------------------------------------
// Launch (dummy first so ncu's fixed capture index lands on main_kernel)
// ---------------------------------------------------------------------------
extern "C" void kernel_launch(void* const* d_in, const int* in_sizes, int n_in,
                              void* d_out, int out_size)
{
    const float* hidden = (const float*)d_in[0];
    const float* enc    = (const float*)d_in[1];
    const float* W_attn = (const float*)d_in[2];
    const float* b_attn = (const float*)d_in[3];
    const float* v      = (const float*)d_in[4];
    float* out = (float*)d_out;

    cudaFuncSetAttribute(main_kernel,
                         cudaFuncAttributeMaxDynamicSharedMemorySize, SMEM_TOTAL);

    dummy_kernel<<<1, 32>>>();
    wconv_kernel<<<1024, 256>>>(W_attn);
    hpart_kernel<<<dim3(Bn, 4), 512>>>(hidden, W_attn, b_attn);
    // grid.x = column blocks so consecutive CTAs share the same A row-tile (L2 dedup)
    main_kernel<<<dim3(NBLK, Mrows / TM), NTHREADS, SMEM_TOTAL>>>(enc, v);
    softmax_kernel<<<Bn, 512>>>(out);
}

// round 9
// speedup vs baseline: 1.0905x; 1.0905x over previous
#include <cuda_runtime.h>
#include <cuda_bf16.h>
#include <math.h>
#include <stdint.h>

// ---------------------------------------------------------------------------
// Problem constants
// ---------------------------------------------------------------------------
#define Hn   512
#define DHn  2048
#define Bn   32
#define Sn   2048
#define Mrows (Sn * Bn)       // 65536

// GEMM tiling: 128x128 tile, KC=32, 3-stage, 2 CTAs/SM
#define TM 128
#define TN 128
#define KC 32
#define NCHUNK (Hn / KC)      // 16
#define NBLK (Hn / TN)        // 4
#define NTHREADS 256
#define NSTAGE 3

// smem: A tile 128x32 f32 (16KB) + B tile 128x32 f32 (16KB) per stage
#define OFF_A 0
#define OFF_B 16384
#define STG_BYTES 32768
#define SMEM_TOTAL (NSTAGE * STG_BYTES)   // 98304 -> 2 CTAs/SM (192KB)

// ---------------------------------------------------------------------------
// Device scratch
// ---------------------------------------------------------------------------
__device__ __align__(16) float g_hpart[Hn * Bn];            // [d][b]
__device__ __align__(16) float g_partial[NBLK * Bn * Sn];   // [j][b][s]
__device__ __align__(16) float g_Wt[Hn * Hn];               // [n][k], tf32-rounded

// ---------------------------------------------------------------------------
// PTX helpers (compute_100-safe, sm_80-era)
// ---------------------------------------------------------------------------
__device__ __forceinline__ uint32_t smem_u32(const void* p) {
    uint32_t a;
    asm("{ .reg .u64 t; cvta.to.shared.u64 t, %1; cvt.u32.u64 %0, t; }"
        : "=r"(a) : "l"(p));
    return a;
}

#define CP16(daddr, sptr) \
    asm volatile("cp.async.cg.shared.global [%0], [%1], 16;" \
        :: "r"((uint32_t)(daddr)), "l"(__cvta_generic_to_global(sptr)))
#define CP_COMMIT() asm volatile("cp.async.commit_group;" ::: "memory")
#define CP_WAIT1()  asm volatile("cp.async.wait_group 1;" ::: "memory")
#define CP_WAIT0()  asm volatile("cp.async.wait_group 0;" ::: "memory")

#define LDSM4(r, addr) \
    asm volatile("ldmatrix.sync.aligned.m8n8.x4.shared.b16 {%0,%1,%2,%3}, [%4];" \
        : "=r"((r)[0]), "=r"((r)[1]), "=r"((r)[2]), "=r"((r)[3]) \
        : "r"((uint32_t)(addr)))

#define MMA_TF32(d, a, b0, b1) \
    asm volatile( \
        "mma.sync.aligned.m16n8k8.row.col.f32.tf32.tf32.f32 " \
        "{%0,%1,%2,%3}, {%4,%5,%6,%7}, {%8,%9}, {%0,%1,%2,%3};" \
        : "+f"((d)[0]), "+f"((d)[1]), "+f"((d)[2]), "+f"((d)[3]) \
        : "r"((a)[0]), "r"((a)[1]), "r"((a)[2]), "r"((a)[3]), \
          "r"(b0), "r"(b1))

#define CVT_TF32(dst, src) \
    asm volatile("cvt.rna.tf32.f32 %0, %1;" : "=r"(dst) : "r"(src))

// ---------------------------------------------------------------------------
// FMA-only fast tanh (no MUFU)
// ---------------------------------------------------------------------------
__device__ __forceinline__ float fast_tanh(float x) {
    const float C = 7.90531110763549805f;
    float xc = fmaxf(-C, fminf(C, x));
    float x2 = xc * xc;
    float p = -2.76076847742355e-16f;
    p = fmaf(p, x2, 2.00018790482477e-13f);
    p = fmaf(p, x2, -8.60467152213735e-11f);
    p = fmaf(p, x2, 5.12229709037114e-08f);
    p = fmaf(p, x2, 1.48572235717979e-05f);
    p = fmaf(p, x2, 6.37261928875436e-04f);
    p = fmaf(p, x2, 4.89352455891786e-03f);
    p = p * xc;
    float q = 1.19825839466702e-06f;
    q = fmaf(q, x2, 1.18534705686654e-04f);
    q = fmaf(q, x2, 2.26843463243900e-03f);
    q = fmaf(q, x2, 4.89352518554385e-03f);
    float y = __uint_as_float(0x7EF311C3u - __float_as_uint(q));
    y = y * fmaf(-q, y, 2.0f);
    y = y * fmaf(-q, y, 2.0f);
    y = y * fmaf(-q, y, 2.0f);
    return p * y;
}

// ---------------------------------------------------------------------------
// Kernel D: no-op (shifts launch index so ncu captures main_kernel)
// ---------------------------------------------------------------------------
__global__ void dummy_kernel() {}

// ---------------------------------------------------------------------------
// Kernel 0: W_e -> transposed, tf32-rounded fp32  g_Wt[n][k]
// ---------------------------------------------------------------------------
__global__ __launch_bounds__(256) void wconv_kernel(const float* __restrict__ W_attn)
{
    int idx = blockIdx.x * 256 + threadIdx.x;   // 0..262143
    int n = idx & (Hn - 1);                     // coalesced read along n
    int k = idx >> 9;
    uint32_t w = __float_as_uint(W_attn[(size_t)(DHn + k) * Hn + n]);
    uint32_t r;
    CVT_TF32(r, w);
    g_Wt[(size_t)n * Hn + k] = __uint_as_float(r);
}

// ---------------------------------------------------------------------------
// Kernel 1: hpart[d][b] = hidden[b] @ W_h[:,d] + b_attn[d]   (transposed out)
// ---------------------------------------------------------------------------
__global__ __launch_bounds__(512) void hpart_kernel(
    const float* __restrict__ hidden,
    const float* __restrict__ W_attn,
    const float* __restrict__ b_attn)
{
    __shared__ float red[3 * 128];
    int tid = threadIdx.x;
    int dl = tid & 127;
    int kh = tid >> 7;                   // 0..3
    int b = blockIdx.x;
    int d = blockIdx.y * 128 + dl;

    const float* __restrict__ hrow = hidden + b * DHn + kh * 512;
    const float* __restrict__ Wp = W_attn + (size_t)(kh * 512) * Hn + d;
    float acc = 0.0f;
#pragma unroll 8
    for (int k = 0; k < 512; k++) {
        acc = fmaf(hrow[k], Wp[(size_t)k * Hn], acc);
    }
    if (kh > 0) red[(kh - 1) * 128 + dl] = acc;
    __syncthreads();
    if (kh == 0) {
        acc += red[dl] + red[128 + dl] + red[256 + dl] + b_attn[d];
        g_hpart[(size_t)d * Bn + b] = acc;
    }
}

// ---------------------------------------------------------------------------
// Kernel 2: single-pass tf32 mma GEMM + tanh + v-dot
// grid (NBLK, 512); 256 threads (8 warps: 2M x 4N); tile 128x128, KC=32
// 3-stage cp.async, 2 CTAs/SM. A fragments fed raw (HW tf32 truncation);
// B pre-rounded rna in wconv — no CVT in the mainloop.
// ---------------------------------------------------------------------------
__global__ __launch_bounds__(NTHREADS, 2) void main_kernel(
    const float* __restrict__ enc,    // (65536, 512) fp32
    const float* __restrict__ v)
{
    extern __shared__ char smem[];
    const uint32_t sb = smem_u32(smem);
    const int tid = threadIdx.x;
    const int wid = tid >> 5;
    const int lane = tid & 31;
    const int warp_m = wid >> 2;          // 0..1
    const int warp_n = wid & 3;           // 0..3
    const int colbase = blockIdx.x * TN;
    const int rowbase = blockIdx.y * TM;

    float acc[4][4][4];
#pragma unroll
    for (int mt = 0; mt < 4; mt++)
#pragma unroll
        for (int nt = 0; nt < 4; nt++)
#pragma unroll
            for (int q = 0; q < 4; q++) acc[mt][nt][q] = 0.0f;

    // cp.async one K-chunk (A 128x32 f32 + B 128x32 f32) into stage s.
    // Row = 128B (8 x 16B units); swizzle: phys_unit = u ^ (row & 7)
    auto load_chunk = [&](int c, int s) {
        const int kb = c * KC;
        const uint32_t stg = sb + s * STG_BYTES;
#pragma unroll
        for (int j = 0; j < 4; j++) {           // A: 1024 units
            int idx = tid + j * NTHREADS;
            int row = idx >> 3;
            int u = idx & 7;
            uint32_t doff = (uint32_t)(row * 128 + 16 * (u ^ (row & 7)));
            CP16(stg + OFF_A + doff, enc + (size_t)(rowbase + row) * Hn + kb + u * 4);
        }
#pragma unroll
        for (int j = 0; j < 4; j++) {           // B: 1024 units
            int idx = tid + j * NTHREADS;
            int row = idx >> 3;
            int u = idx & 7;
            uint32_t doff = (uint32_t)(row * 128 + 16 * (u ^ (row & 7)));
            CP16(stg + OFF_B + doff, g_Wt + (size_t)(colbase + row) * Hn + kb + u * 4);
        }
    };

    load_chunk(0, 0);
    CP_COMMIT();
    load_chunk(1, 1);
    CP_COMMIT();

    // ldmatrix per-lane addressing (32-bit elements via b16 ldmatrix)
    const int a_r  = ((lane >> 3) & 1) * 8 + (lane & 7);  // row within m16
    const int a_uo = (lane >> 4);                         // 16B-unit offset 0/1
    const int b_r  = ((lane >> 4) & 1) * 8 + (lane & 7);  // n within 16
    const int b_uo = ((lane >> 3) & 1);

    int stage_c = 0;        // stage holding chunk c
    int stage_l = 2;        // stage for chunk c+2

    for (int c = 0; c < NCHUNK; c++) {
        if (c < NCHUNK - 1) { CP_WAIT1(); } else { CP_WAIT0(); }
        __syncthreads();
        if (c + 2 < NCHUNK) {
            load_chunk(c + 2, stage_l);
            CP_COMMIT();
        }

        const uint32_t stg = sb + stage_c * STG_BYTES;
        const uint32_t sA = stg + OFF_A;
        const uint32_t sB = stg + OFF_B;

#pragma unroll
        for (int ks = 0; ks < 4; ks++) {        // 4 k8-steps per 32-chunk
            const int ub = ks * 2;
            uint32_t afr[4][4], bfr[2][4];
#pragma unroll
            for (int mt = 0; mt < 4; mt++) {
                int row = warp_m * 64 + mt * 16 + a_r;
                uint32_t off = (uint32_t)(row * 128 + 16 * ((ub + a_uo) ^ (row & 7)));
                LDSM4(afr[mt], sA + off);
            }
#pragma unroll
            for (int pr = 0; pr < 2; pr++) {
                int n = warp_n * 32 + pr * 16 + b_r;
                uint32_t off = (uint32_t)(n * 128 + 16 * ((ub + b_uo) ^ (n & 7)));
                LDSM4(bfr[pr], sB + off);
            }
            // NOTE: no cvt — HW truncates f32->tf32 on A; B is pre-rounded rna.
#pragma unroll
            for (int mt = 0; mt < 4; mt++) {
#pragma unroll
                for (int pr = 0; pr < 2; pr++) {
                    MMA_TF32(acc[mt][pr * 2 + 0], afr[mt], bfr[pr][0], bfr[pr][1]);
                    MMA_TF32(acc[mt][pr * 2 + 1], afr[mt], bfr[pr][2], bfr[pr][3]);
                }
            }
        }

        stage_c = (stage_c == 2) ? 0 : stage_c + 1;
        stage_l = (stage_l == 2) ? 0 : stage_l + 1;
    }

    __syncthreads();   // all reads done before smem reuse

    // ---- Epilogue: hp[col][b] (16KB), v (512B), red (128x17 = 8.7KB)
    float* hp_s = (float*)smem;                        // 128*32
    float* v_s  = (float*)(smem + 16384);              // 128
    float* red  = (float*)(smem + 17408);              // 128*17

    for (int i = tid; i < TN * Bn; i += NTHREADS)
        hp_s[i] = g_hpart[(size_t)colbase * Bn + i];
    if (tid < TN) v_s[tid] = v[colbase + tid];
    __syncthreads();

    const int tg = lane & 3;
    const int gid = lane >> 2;
#pragma unroll
    for (int mt = 0; mt < 4; mt++) {
        int r0 = warp_m * 64 + mt * 16 + gid;
        int r1 = r0 + 8;
        int b0 = r0 & 31;
        int b1 = r1 & 31;
        float s0 = 0.0f, s1 = 0.0f;
#pragma unroll
        for (int nt = 0; nt < 4; nt++) {
            int c0 = warp_n * 32 + nt * 8 + tg * 2;
            float v0 = v_s[c0], v1 = v_s[c0 + 1];
            float x00 = acc[mt][nt][0] + hp_s[c0 * 32 + b0];
            float x10 = acc[mt][nt][1] + hp_s[(c0 + 1) * 32 + b0];
            float x01 = acc[mt][nt][2] + hp_s[c0 * 32 + b1];
            float x11 = acc[mt][nt][3] + hp_s[(c0 + 1) * 32 + b1];
            s0 = fmaf(fast_tanh(x00), v0, s0);
            s0 = fmaf(fast_tanh(x10), v1, s0);
            s1 = fmaf(fast_tanh(x01), v0, s1);
            s1 = fmaf(fast_tanh(x11), v1, s1);
        }
        red[r0 * 17 + warp_n * 4 + tg] = s0;
        red[r1 * 17 + warp_n * 4 + tg] = s1;
    }
    __syncthreads();

    if (tid < TM) {
        float s = 0.0f;
#pragma unroll
        for (int j = 0; j < 16; j++) s += red[tid * 17 + j];
        int b = tid & 31;
        int seq = blockIdx.y * (TM / Bn) + (tid >> 5);
        g_partial[blockIdx.x * (Bn * Sn) + b * Sn + seq] = s;
    }
}

// ---------------------------------------------------------------------------
// Kernel 3: sum 4 partials + softmax over s
// ---------------------------------------------------------------------------
__global__ __launch_bounds__(512) void softmax_kernel(float* __restrict__ out)
{
    const int b = blockIdx.x;
    const int tid = threadIdx.x;
    __shared__ float logits[Sn];
    __shared__ float redbuf[512];

    for (int s = tid; s < Sn; s += 512) {
        float t = 0.0f;
#pragma unroll
        for (int j = 0; j < NBLK; j++) t += g_partial[j * (Bn * Sn) + b * Sn + s];
        logits[s] = t;
    }
    __syncthreads();

    float m = -INFINITY;
    for (int s = tid; s < Sn; s += 512) m = fmaxf(m, logits[s]);
    redbuf[tid] = m;
    __syncthreads();
    for (int off = 256; off > 0; off >>= 1) {
        if (tid < off) redbuf[tid] = fmaxf(redbuf[tid], redbuf[tid + off]);
        __syncthreads();
    }
    m = redbuf[0];
    __syncthreads();

    float sum = 0.0f;
    for (int s = tid; s < Sn; s += 512) {
        float e = expf(logits[s] - m);
        logits[s] = e;
        sum += e;
    }
    redbuf[tid] = sum;
    __syncthreads();
    for (int off = 256; off > 0; off >>= 1) {
        if (tid < off) redbuf[tid] += redbuf[tid + off];
        __syncthreads();
    }
    const float inv = 1.0f / redbuf[0];
    __syncthreads();

    for (int s = tid; s < Sn; s += 512) {
        out[b * Sn + s] = logits[s] * inv;
    }
}

// ---------------------------------------------------------------------------
// Launch (dummy first so ncu's fixed capture index lands on main_kernel)
// ---------------------------------------------------------------------------
extern "C" void kernel_launch(void* const* d_in, const int* in_sizes, int n_in,
                              void* d_out, int out_size)
{
    const float* hidden = (const float*)d_in[0];
    const float* enc    = (const float*)d_in[1];
    const float* W_attn = (const float*)d_in[2];
    const float* b_attn = (const float*)d_in[3];
    const float* v      = (const float*)d_in[4];
    float* out = (float*)d_out;

    cudaFuncSetAttribute(main_kernel,
                         cudaFuncAttributeMaxDynamicSharedMemorySize, SMEM_TOTAL);

    dummy_kernel<<<1, 32>>>();
    wconv_kernel<<<1024, 256>>>(W_attn);
    hpart_kernel<<<dim3(Bn, 4), 512>>>(hidden, W_attn, b_attn);
    // grid.x = column blocks so consecutive CTAs share the same A row-tile (L2 dedup)
    main_kernel<<<dim3(NBLK, Mrows / TM), NTHREADS, SMEM_TOTAL>>>(enc, v);
    softmax_kernel<<<Bn, 512>>>(out);
}

// round 10
// speedup vs baseline: 1.0965x; 1.0055x over previous
#include <cuda_runtime.h>
#include <cuda_bf16.h>
#include <math.h>
#include <stdint.h>

// ---------------------------------------------------------------------------
// Problem constants
// ---------------------------------------------------------------------------
#define Hn   512
#define DHn  2048
#define Bn   32
#define Sn   2048
#define Mrows (Sn * Bn)       // 65536

// GEMM tiling: 128x128 tile, KC=32, 3-stage, 2 CTAs/SM
#define TM 128
#define TN 128
#define KC 32
#define NCHUNK (Hn / KC)      // 16
#define NBLK (Hn / TN)        // 4
#define NTHREADS 256
#define NSTAGE 3

// smem: A tile 128x32 f32 (16KB) + B tile 128x32 f32 (16KB) per stage
#define OFF_A 0
#define OFF_B 16384
#define STG_BYTES 32768
#define SMEM_TOTAL (NSTAGE * STG_BYTES)   // 98304 -> 2 CTAs/SM (192KB)

// ---------------------------------------------------------------------------
// Device scratch
// ---------------------------------------------------------------------------
__device__ __align__(16) float g_hpart[Hn * Bn];            // [d][b]
__device__ __align__(16) float g_partial[NBLK * Bn * Sn];   // [j][b][s]
__device__ __align__(16) float g_Wt[Hn * Hn];               // [n][k], tf32-rounded

// ---------------------------------------------------------------------------
// PTX helpers (compute_100-safe, sm_80-era)
// ---------------------------------------------------------------------------
__device__ __forceinline__ uint32_t smem_u32(const void* p) {
    uint32_t a;
    asm("{ .reg .u64 t; cvta.to.shared.u64 t, %1; cvt.u32.u64 %0, t; }"
        : "=r"(a) : "l"(p));
    return a;
}

#define CP16(daddr, sptr) \
    asm volatile("cp.async.cg.shared.global [%0], [%1], 16;" \
        :: "r"((uint32_t)(daddr)), "l"(__cvta_generic_to_global(sptr)))
#define CP_COMMIT() asm volatile("cp.async.commit_group;" ::: "memory")
#define CP_WAIT1()  asm volatile("cp.async.wait_group 1;" ::: "memory")
#define CP_WAIT0()  asm volatile("cp.async.wait_group 0;" ::: "memory")

#define LDSM4(r, addr) \
    asm volatile("ldmatrix.sync.aligned.m8n8.x4.shared.b16 {%0,%1,%2,%3}, [%4];" \
        : "=r"((r)[0]), "=r"((r)[1]), "=r"((r)[2]), "=r"((r)[3]) \
        : "r"((uint32_t)(addr)))

#define MMA_TF32(d, a, b0, b1) \
    asm volatile( \
        "mma.sync.aligned.m16n8k8.row.col.f32.tf32.tf32.f32 " \
        "{%0,%1,%2,%3}, {%4,%5,%6,%7}, {%8,%9}, {%0,%1,%2,%3};" \
        : "+f"((d)[0]), "+f"((d)[1]), "+f"((d)[2]), "+f"((d)[3]) \
        : "r"((a)[0]), "r"((a)[1]), "r"((a)[2]), "r"((a)[3]), \
          "r"(b0), "r"(b1))

#define CVT_TF32(dst, src) \
    asm volatile("cvt.rna.tf32.f32 %0, %1;" : "=r"(dst) : "r"(src))

// ---------------------------------------------------------------------------
// FMA-only fast tanh (no MUFU)
// ---------------------------------------------------------------------------
__device__ __forceinline__ float fast_tanh(float x) {
    const float C = 7.90531110763549805f;
    float xc = fmaxf(-C, fminf(C, x));
    float x2 = xc * xc;
    float p = -2.76076847742355e-16f;
    p = fmaf(p, x2, 2.00018790482477e-13f);
    p = fmaf(p, x2, -8.60467152213735e-11f);
    p = fmaf(p, x2, 5.12229709037114e-08f);
    p = fmaf(p, x2, 1.48572235717979e-05f);
    p = fmaf(p, x2, 6.37261928875436e-04f);
    p = fmaf(p, x2, 4.89352455891786e-03f);
    p = p * xc;
    float q = 1.19825839466702e-06f;
    q = fmaf(q, x2, 1.18534705686654e-04f);
    q = fmaf(q, x2, 2.26843463243900e-03f);
    q = fmaf(q, x2, 4.89352518554385e-03f);
    float y = __uint_as_float(0x7EF311C3u - __float_as_uint(q));
    y = y * fmaf(-q, y, 2.0f);
    y = y * fmaf(-q, y, 2.0f);
    y = y * fmaf(-q, y, 2.0f);
    return p * y;
}

// ---------------------------------------------------------------------------
// Kernel D: no-op (shifts launch index so ncu captures main_kernel)
// ---------------------------------------------------------------------------
__global__ void dummy_kernel() {}

// ---------------------------------------------------------------------------
// Kernel 0: W_e -> transposed, tf32-rounded fp32  g_Wt[n][k]
// ---------------------------------------------------------------------------
__global__ __launch_bounds__(256) void wconv_kernel(const float* __restrict__ W_attn)
{
    int idx = blockIdx.x * 256 + threadIdx.x;   // 0..262143
    int n = idx & (Hn - 1);                     // coalesced read along n
    int k = idx >> 9;
    uint32_t w = __float_as_uint(W_attn[(size_t)(DHn + k) * Hn + n]);
    uint32_t r;
    CVT_TF32(r, w);
    g_Wt[(size_t)n * Hn + k] = __uint_as_float(r);
}

// ---------------------------------------------------------------------------
// Kernel 1: hpart[d][b] = hidden[b] @ W_h[:,d] + b_attn[d]   (transposed out)
// ---------------------------------------------------------------------------
__global__ __launch_bounds__(512) void hpart_kernel(
    const float* __restrict__ hidden,
    const float* __restrict__ W_attn,
    const float* __restrict__ b_attn)
{
    __shared__ float red[3 * 128];
    int tid = threadIdx.x;
    int dl = tid & 127;
    int kh = tid >> 7;                   // 0..3
    int b = blockIdx.x;
    int d = blockIdx.y * 128 + dl;

    const float* __restrict__ hrow = hidden + b * DHn + kh * 512;
    const float* __restrict__ Wp = W_attn + (size_t)(kh * 512) * Hn + d;
    float acc = 0.0f;
#pragma unroll 8
    for (int k = 0; k < 512; k++) {
        acc = fmaf(hrow[k], Wp[(size_t)k * Hn], acc);
    }
    if (kh > 0) red[(kh - 1) * 128 + dl] = acc;
    __syncthreads();
    if (kh == 0) {
        acc += red[dl] + red[128 + dl] + red[256 + dl] + b_attn[d];
        g_hpart[(size_t)d * Bn + b] = acc;
    }
}

// ---------------------------------------------------------------------------
// Kernel 2: single-pass tf32 mma GEMM + tanh + v-dot
// grid (NBLK, 512); 256 threads (8 warps: 2M x 4N); tile 128x128, KC=32
// 3-stage cp.async, 2 CTAs/SM, k-step fragment double-buffering.
// Swizzled ldmatrix addresses obey addr(ks) = addr(0) XOR (32*ks) and
// addr0[mt] = addr0[0] + 2048*mt  -> only 2 live address registers.
// ---------------------------------------------------------------------------
__global__ __launch_bounds__(NTHREADS, 2) void main_kernel(
    const float* __restrict__ enc,    // (65536, 512) fp32
    const float* __restrict__ v)
{
    extern __shared__ char smem[];
    const uint32_t sb = smem_u32(smem);
    const int tid = threadIdx.x;
    const int wid = tid >> 5;
    const int lane = tid & 31;
    const int warp_m = wid >> 2;          // 0..1
    const int warp_n = wid & 3;           // 0..3
    const int colbase = blockIdx.x * TN;
    const int rowbase = blockIdx.y * TM;

    float acc[4][4][4];
#pragma unroll
    for (int mt = 0; mt < 4; mt++)
#pragma unroll
        for (int nt = 0; nt < 4; nt++)
#pragma unroll
            for (int q = 0; q < 4; q++) acc[mt][nt][q] = 0.0f;

    // cp.async one K-chunk (A 128x32 f32 + B 128x32 f32) into stage s.
    auto load_chunk = [&](int c, int s) {
        const int kb = c * KC;
        const uint32_t stg = sb + s * STG_BYTES;
#pragma unroll
        for (int j = 0; j < 4; j++) {           // A: 1024 units
            int idx = tid + j * NTHREADS;
            int row = idx >> 3;
            int u = idx & 7;
            uint32_t doff = (uint32_t)(row * 128 + 16 * (u ^ (row & 7)));
            CP16(stg + OFF_A + doff, enc + (size_t)(rowbase + row) * Hn + kb + u * 4);
        }
#pragma unroll
        for (int j = 0; j < 4; j++) {           // B: 1024 units
            int idx = tid + j * NTHREADS;
            int row = idx >> 3;
            int u = idx & 7;
            uint32_t doff = (uint32_t)(row * 128 + 16 * (u ^ (row & 7)));
            CP16(stg + OFF_B + doff, g_Wt + (size_t)(colbase + row) * Hn + kb + u * 4);
        }
    };

    load_chunk(0, 0);
    CP_COMMIT();
    load_chunk(1, 1);
    CP_COMMIT();

    // ldmatrix per-lane base addressing (ks = 0, mt = 0 / pr = 0)
    const int a_r  = ((lane >> 3) & 1) * 8 + (lane & 7);  // row within m16
    const int a_uo = (lane >> 4);                         // 16B-unit offset 0/1
    const int b_r  = ((lane >> 4) & 1) * 8 + (lane & 7);  // n within 16
    const int b_uo = ((lane >> 3) & 1);

    const int arow0 = warp_m * 64 + a_r;
    const int brow0 = warp_n * 32 + b_r;
    // offsets within a stage (ks=0); full addr = stagebase + this
    const uint32_t aoff0 = (uint32_t)(arow0 * 128 + 16 * (a_uo ^ (arow0 & 7))) + OFF_A;
    const uint32_t boff0 = (uint32_t)(brow0 * 128 + 16 * (b_uo ^ (brow0 & 7))) + OFF_B;

    uint32_t afr[2][4][4], bfr[2][2][4];

    int stage_c = 0;        // stage holding chunk c
    int stage_l = 2;        // stage for chunk c+2

    for (int c = 0; c < NCHUNK; c++) {
        if (c < NCHUNK - 1) { CP_WAIT1(); } else { CP_WAIT0(); }
        __syncthreads();
        if (c + 2 < NCHUNK) {
            load_chunk(c + 2, stage_l);
            CP_COMMIT();
        }

        const uint32_t sa0 = sb + stage_c * STG_BYTES + aoff0;  // A, mt0, ks0
        const uint32_t sb0 = sb + stage_c * STG_BYTES + boff0;  // B, pr0, ks0

        auto ld_frags = [&](int ks, int buf) {
            const uint32_t kx = (uint32_t)(ks * 32);
#pragma unroll
            for (int mt = 0; mt < 4; mt++)
                LDSM4(afr[buf][mt], (sa0 + mt * 2048) ^ kx);
#pragma unroll
            for (int pr = 0; pr < 2; pr++)
                LDSM4(bfr[buf][pr], (sb0 + pr * 2048) ^ kx);
        };

        ld_frags(0, 0);
#pragma unroll
        for (int ks = 0; ks < 4; ks++) {
            if (ks < 3) ld_frags(ks + 1, (ks + 1) & 1);
            const int buf = ks & 1;
#pragma unroll
            for (int mt = 0; mt < 4; mt++) {
#pragma unroll
                for (int pr = 0; pr < 2; pr++) {
                    MMA_TF32(acc[mt][pr * 2 + 0], afr[buf][mt], bfr[buf][pr][0], bfr[buf][pr][1]);
                    MMA_TF32(acc[mt][pr * 2 + 1], afr[buf][mt], bfr[buf][pr][2], bfr[buf][pr][3]);
                }
            }
        }

        stage_c = (stage_c == 2) ? 0 : stage_c + 1;
        stage_l = (stage_l == 2) ? 0 : stage_l + 1;
    }

    __syncthreads();   // all reads done before smem reuse

    // ---- Epilogue: hp[col][b] (16KB), v (512B), red (128x17 = 8.7KB)
    float* hp_s = (float*)smem;                        // 128*32
    float* v_s  = (float*)(smem + 16384);              // 128
    float* red  = (float*)(smem + 17408);              // 128*17

    for (int i = tid; i < TN * Bn; i += NTHREADS)
        hp_s[i] = g_hpart[(size_t)colbase * Bn + i];
    if (tid < TN) v_s[tid] = v[colbase + tid];
    __syncthreads();

    const int tg = lane & 3;
    const int gid = lane >> 2;
#pragma unroll
    for (int mt = 0; mt < 4; mt++) {
        int r0 = warp_m * 64 + mt * 16 + gid;
        int r1 = r0 + 8;
        int b0 = r0 & 31;
        int b1 = r1 & 31;
        float s0 = 0.0f, s1 = 0.0f;
#pragma unroll
        for (int nt = 0; nt < 4; nt++) {
            int c0 = warp_n * 32 + nt * 8 + tg * 2;
            float v0 = v_s[c0], v1 = v_s[c0 + 1];
            float x00 = acc[mt][nt][0] + hp_s[c0 * 32 + b0];
            float x10 = acc[mt][nt][1] + hp_s[(c0 + 1) * 32 + b0];
            float x01 = acc[mt][nt][2] + hp_s[c0 * 32 + b1];
            float x11 = acc[mt][nt][3] + hp_s[(c0 + 1) * 32 + b1];
            s0 = fmaf(fast_tanh(x00), v0, s0);
            s0 = fmaf(fast_tanh(x10), v1, s0);
            s1 = fmaf(fast_tanh(x01), v0, s1);
            s1 = fmaf(fast_tanh(x11), v1, s1);
        }
        red[r0 * 17 + warp_n * 4 + tg] = s0;
        red[r1 * 17 + warp_n * 4 + tg] = s1;
    }
    __syncthreads();

    if (tid < TM) {
        float s = 0.0f;
#pragma unroll
        for (int j = 0; j < 16; j++) s += red[tid * 17 + j];
        int b = tid & 31;
        int seq = blockIdx.y * (TM / Bn) + (tid >> 5);
        g_partial[blockIdx.x * (Bn * Sn) + b * Sn + seq] = s;
    }
}

// ---------------------------------------------------------------------------
// Kernel 3: sum 4 partials + softmax over s
// ---------------------------------------------------------------------------
__global__ __launch_bounds__(512) void softmax_kernel(float* __restrict__ out)
{
    const int b = blockIdx.x;
    const int tid = threadIdx.x;
    __shared__ float logits[Sn];
    __shared__ float redbuf[512];

    for (int s = tid; s < Sn; s += 512) {
        float t = 0.0f;
#pragma unroll
        for (int j = 0; j < NBLK; j++) t += g_partial[j * (Bn * Sn) + b * Sn + s];
        logits[s] = t;
    }
    __syncthreads();

    float m = -INFINITY;
    for (int s = tid; s < Sn; s += 512) m = fmaxf(m, logits[s]);
    redbuf[tid] = m;
    __syncthreads();
    for (int off = 256; off > 0; off >>= 1) {
        if (tid < off) redbuf[tid] = fmaxf(redbuf[tid], redbuf[tid + off]);
        __syncthreads();
    }
    m = redbuf[0];
    __syncthreads();

    float sum = 0.0f;
    for (int s = tid; s < Sn; s += 512) {
        float e = expf(logits[s] - m);
        logits[s] = e;
        sum += e;
    }
    redbuf[tid] = sum;
    __syncthreads();
    for (int off = 256; off > 0; off >>= 1) {
        if (tid < off) redbuf[tid] += redbuf[tid + off];
        __syncthreads();
    }
    const float inv = 1.0f / redbuf[0];
    __syncthreads();

    for (int s = tid; s < Sn; s += 512) {
        out[b * Sn + s] = logits[s] * inv;
    }
}

// ---------------------------------------------------------------------------
// Launch (dummy first so ncu's fixed capture index lands on main_kernel)
// ---------------------------------------------------------------------------
extern "C" void kernel_launch(void* const* d_in, const int* in_sizes, int n_in,
                              void* d_out, int out_size)
{
    const float* hidden = (const float*)d_in[0];
    const float* enc    = (const float*)d_in[1];
    const float* W_attn = (const float*)d_in[2];
    const float* b_attn = (const float*)d_in[3];
    const float* v      = (const float*)d_in[4];
    float* out = (float*)d_out;

    cudaFuncSetAttribute(main_kernel,
                         cudaFuncAttributeMaxDynamicSharedMemorySize, SMEM_TOTAL);

    dummy_kernel<<<1, 32>>>();
    wconv_kernel<<<1024, 256>>>(W_attn);
    hpart_kernel<<<dim3(Bn, 4), 512>>>(hidden, W_attn, b_attn);
    // grid.x = column blocks so consecutive CTAs share the same A row-tile (L2 dedup)
    main_kernel<<<dim3(NBLK, Mrows / TM), NTHREADS, SMEM_TOTAL>>>(enc, v);
    softmax_kernel<<<Bn, 512>>>(out);
}